// round 7
// baseline (speedup 1.0000x reference)
#include <cuda_runtime.h>
#include <cstdint>

#define NCOUNT 8
#define B_TOTAL 16384
#define L1 3072
#define M_TILE 128
#define KCHUNK 64
#define NCHUNK 48
#define MAX_TILES 136
#define NTHREADS 256
#define NSTAGE 4
#define ROW_STRIDE 272u                     // 256B data + 16B stagger (bank spread)
#define X_BYTES (128u * ROW_STRIDE)         // 34816
#define STAGE_BYTES (X_BYTES + 16u * ROW_STRIDE)   // 39168
#define TX_BYTES (144u * 256u)              // 36864 expected bytes per stage fill

// ---------------- device scratch ----------------
__device__ int   g_fill[NCOUNT];            // zeroed at load; re-zeroed by k_main blk0
__device__ int   g_rows2[NCOUNT][B_TOTAL];
__device__ float g_wcomb[NCOUNT * 16 * L1]; // combined l1_w[bucket] + l1f_w

#define FMA2(d, a, b) asm("fma.rn.f32x2 %0, %1, %2, %0;" : "+l"(d) : "l"(a), "l"(b))

__device__ __forceinline__ uint32_t smem_u32(const void* p) {
    return (uint32_t)__cvta_generic_to_shared((void*)p);
}

__device__ __forceinline__ void mbar_wait(uint32_t addr, uint32_t parity) {
    uint32_t done;
    asm volatile(
        "{\n\t.reg .pred p;\n\t"
        "mbarrier.try_wait.parity.acquire.cta.shared::cta.b64 p, [%1], %2;\n\t"
        "selp.b32 %0, 1, 0, p;\n\t}"
        : "=r"(done) : "r"(addr), "r"(parity) : "memory");
    if (!done) {
        asm volatile(
            "{\n\t.reg .pred P1;\n\t"
            "WL%=:\n\t"
            "mbarrier.try_wait.parity.acquire.cta.shared::cta.b64 P1, [%0], %1, 0x989680;\n\t"
            "@P1 bra.uni WD%=;\n\t"
            "bra.uni WL%=;\n\t"
            "WD%=:\n\t}"
            :: "r"(addr), "r"(parity) : "memory");
    }
}

// ---------------- prep: combined weights + bucket scatter ----------------
__global__ void k_prep(const float* __restrict__ l1w, const float* __restrict__ l1fw,
                       const int* __restrict__ idx)
{
    if (blockIdx.x < 768) {
        int e = blockIdx.x * 512 + threadIdx.x;     // 768*512 == 8*16*3072 exactly
        int k = e % L1;
        int r = (e / L1) % 16;
        g_wcomb[e] = l1w[e] + l1fw[r * L1 + k];
    } else {
        __shared__ int s_cnt[NCOUNT];
        __shared__ int s_base[NCOUNT];
        int tid = threadIdx.x;
        int i = (blockIdx.x - 768) * 512 + tid;
        int lane = tid & 31;
        if (tid < NCOUNT) s_cnt[tid] = 0;
        __syncthreads();
        int c = idx[i];
        unsigned mask = __match_any_sync(0xffffffffu, c);
        int leader = __ffs(mask) - 1;
        int rank = __popc(mask & ((1u << lane) - 1u));
        int wb = 0;
        if (lane == leader) wb = atomicAdd(&s_cnt[c], __popc(mask));
        wb = __shfl_sync(mask, wb, leader);
        __syncthreads();
        if (tid < NCOUNT) s_base[tid] = s_cnt[tid] ? atomicAdd(&g_fill[tid], s_cnt[tid]) : 0;
        __syncthreads();
        g_rows2[c][s_base[c] + wb + rank] = i;
    }
}

// ---------------- main kernel ----------------
// dyn smem: 4 stages x [x: 128 rows * 272B | w: 16 rows * 272B] = 156672 B
extern __shared__ char s_dyn_raw[];

__global__ void __launch_bounds__(NTHREADS, 1)
k_main(const float* __restrict__ x,
       const float* __restrict__ l1b, const float* __restrict__ l1fb,
       const float* __restrict__ l2w, const float* __restrict__ l2b,
       const float* __restrict__ outw, const float* __restrict__ outb,
       float* __restrict__ out)
{
    const int tid = threadIdx.x;

    // ---- tile -> (bucket, start, rows) from bucket counts ----
    int bucket = -1, startrow = 0, rows = 0;
    {
        int t = blockIdx.x;
#pragma unroll
        for (int c = 0; c < NCOUNT; c++) {
            int n = __ldg(&g_fill[c]);
            int nt = (n + M_TILE - 1) / M_TILE;
            if (bucket < 0) {
                if (t < nt) {
                    bucket = c; startrow = t * M_TILE;
                    rows = n - startrow; if (rows > M_TILE) rows = M_TILE;
                } else t -= nt;
            }
        }
    }
    if (bucket < 0) return;

    __shared__ int   s_rows[M_TILE];
    __shared__ float s_wpad[1024];
    __shared__ float s_outw[32], s_l2b[32], s_bc[16];
    __shared__ float s_outb;
    __shared__ __align__(8) unsigned long long s_mbar[NSTAGE];

    if (tid < M_TILE) {
        int mi = tid < rows ? tid : rows - 1;
        s_rows[tid] = g_rows2[bucket][startrow + mi];
    }
#pragma unroll
    for (int i = 0; i < 4; i++) {
        int e = tid + NTHREADS * i;
        int o = e >> 5, j = e & 31;
        s_wpad[e] = (j < 30) ? l2w[(bucket * 32 + o) * 30 + j] : 0.f;
    }
    if (tid < 32) { s_outw[tid] = outw[bucket * 32 + tid]; s_l2b[tid] = l2b[bucket * 32 + tid]; }
    if (tid < 16) s_bc[tid] = l1b[bucket * 16 + tid] + l1fb[tid];
    if (tid == 0) {
        s_outb = outb[bucket];
#pragma unroll
        for (int s = 0; s < NSTAGE; s++)
            asm volatile("mbarrier.init.shared.b64 [%0], %1;"
                         :: "r"(smem_u32(&s_mbar[s])), "r"(1u) : "memory");
    }
    __syncthreads();

    char*    db   = s_dyn_raw;
    uint32_t db_u = smem_u32(db);
    uint32_t mb_addr[NSTAGE];
#pragma unroll
    for (int s = 0; s < NSTAGE; s++) mb_addr[s] = smem_u32(&s_mbar[s]);

    // loader: tid<128 -> x row tid; tid in [128,144) -> w row tid-128
    const float* ldsrc = 0;
    uint32_t     lddst_off = 0;
    if (tid < 128) {
        ldsrc = x + (size_t)s_rows[tid] * L1;
        lddst_off = (uint32_t)tid * ROW_STRIDE;
    } else if (tid < 144) {
        ldsrc = g_wcomb + (size_t)(bucket * 16 + (tid - 128)) * L1;
        lddst_off = X_BYTES + (uint32_t)(tid - 128) * ROW_STRIDE;
    }

#define ISSUE(cc)                                                                      \
    do {                                                                               \
        if (tid == 0)                                                                  \
            asm volatile("mbarrier.arrive.expect_tx.shared.b64 _, [%0], %1;"           \
                         :: "r"(mb_addr[(cc) & (NSTAGE - 1)]), "r"((uint32_t)TX_BYTES) \
                         : "memory");                                                  \
        if (tid < 144) {                                                               \
            uint32_t dst_ = db_u + (uint32_t)((cc) & (NSTAGE - 1)) * STAGE_BYTES       \
                          + lddst_off;                                                 \
            const float* src_ = ldsrc + (cc) * KCHUNK;                                 \
            asm volatile(                                                              \
                "cp.async.bulk.shared::cluster.global.mbarrier::complete_tx::bytes "   \
                "[%0], [%1], %2, [%3];"                                                \
                :: "r"(dst_), "l"(src_), "r"(256u),                                    \
                   "r"(mb_addr[(cc) & (NSTAGE - 1)]) : "memory");                      \
        }                                                                              \
    } while (0)

    ISSUE(0); ISSUE(1); ISSUE(2); ISSUE(3);

    // compute assignment: 8 warps = 8 k-split groups
    const int ks = tid >> 5;           // k-split 0..7 (2 float4 each)
    const int ng = (tid >> 4) & 1;     // 2 j-groups of 8
    const int mg = tid & 15;           // rows mg + 16r
    const int j0 = ng * 8;

    unsigned long long acc[8][8];
#pragma unroll
    for (int r = 0; r < 8; r++)
#pragma unroll
        for (int s = 0; s < 8; s++) acc[r][s] = 0ull;

#pragma unroll 1
    for (int c = 0; c < NCHUNK; c++) {
        const int stg = c & (NSTAGE - 1);
        mbar_wait(mb_addr[stg], (uint32_t)((c / NSTAGE) & 1));

        const char* xb = db + (uint32_t)stg * STAGE_BYTES;
        const char* wb = xb + X_BYTES;

#pragma unroll
        for (int i = 0; i < 2; i++) {
            int k4 = ks * 2 + i;                 // 0..15
            ulonglong2 wv[8];
#pragma unroll
            for (int s = 0; s < 8; s++)
                wv[s] = *(const ulonglong2*)(wb + (uint32_t)(j0 + s) * ROW_STRIDE + k4 * 16);
#pragma unroll
            for (int r = 0; r < 8; r++) {
                ulonglong2 xv = *(const ulonglong2*)(xb + (uint32_t)(mg + 16 * r) * ROW_STRIDE + k4 * 16);
#pragma unroll
                for (int s = 0; s < 8; s++) {
                    FMA2(acc[r][s], xv.x, wv[s].x);
                    FMA2(acc[r][s], xv.y, wv[s].y);
                }
            }
        }

        __syncthreads();                 // all readers done with stage before refill
        if (c + NSTAGE < NCHUNK) ISSUE(c + NSTAGE);
    }

    // ---- reduce k-split partials via smem (overlay on stage buffers; all bulk done) ----
    float* accs = (float*)s_dyn_raw;   // 8 * 128 * 17 floats = 69632 B
#pragma unroll
    for (int r = 0; r < 8; r++)
#pragma unroll
        for (int s = 0; s < 8; s++) {
            union { unsigned long long u; float2 f; } cv;
            cv.u = acc[r][s];
            accs[ks * 2176 + (mg + 16 * r) * 17 + (j0 + s)] = cv.f.x + cv.f.y;
        }
    __syncthreads();

    // ---- fused stage 2/3: one row per thread ----
    if (tid < M_TILE) {
        float t[16];
#pragma unroll
        for (int j = 0; j < 16; j++) {
            float a = 0.f;
#pragma unroll
            for (int p = 0; p < 8; p++) a += accs[p * 2176 + tid * 17 + j];
            t[j] = a + s_bc[j];
        }

        float v[32];
#pragma unroll
        for (int j = 0; j < 15; j++) {
            float a = t[j];
            v[j]      = fminf(a * a * (127.0f / 128.0f), 1.0f);
            v[15 + j] = fminf(fmaxf(a, 0.0f), 1.0f);
        }
        v[30] = 0.f; v[31] = 0.f;

        float res = t[15] + s_outb;
        const float4* wp4 = (const float4*)s_wpad;
#pragma unroll
        for (int o = 0; o < 32; o++) {
            float s = s_l2b[o];
#pragma unroll
            for (int q = 0; q < 8; q++) {
                float4 w = wp4[o * 8 + q];
                s += w.x * v[q * 4] + w.y * v[q * 4 + 1] + w.z * v[q * 4 + 2] + w.w * v[q * 4 + 3];
            }
            s = fminf(fmaxf(s, 0.0f), 1.0f);
            res += s * s_outw[o];
        }
        if (tid < rows) out[s_rows[tid]] = res;
    }

    __syncthreads();
    if (tid == 0) {
#pragma unroll
        for (int s = 0; s < NSTAGE; s++)
            asm volatile("mbarrier.inval.shared.b64 [%0];" :: "r"(mb_addr[s]) : "memory");
    }
    // reset bucket counters for the next graph replay (single co-resident wave)
    if (blockIdx.x == 0 && tid < NCOUNT) g_fill[tid] = 0;
}

// ---------------- launcher ----------------
extern "C" void kernel_launch(void* const* d_in, const int* in_sizes, int n_in,
                              void* d_out, int out_size)
{
    const float* x    = (const float*)d_in[0];
    const int*   idx  = (const int*)  d_in[1];
    const float* l1w  = (const float*)d_in[2];
    const float* l1b  = (const float*)d_in[3];
    const float* l1fw = (const float*)d_in[4];
    const float* l1fb = (const float*)d_in[5];
    const float* l2w  = (const float*)d_in[6];
    const float* l2b  = (const float*)d_in[7];
    const float* outw = (const float*)d_in[8];
    const float* outb = (const float*)d_in[9];
    float* out = (float*)d_out;

    static bool attr_set = false;
    if (!attr_set) {
        cudaFuncSetAttribute(k_main, cudaFuncAttributeMaxDynamicSharedMemorySize,
                             NSTAGE * STAGE_BYTES + 1024);
        attr_set = true;
    }

    k_prep<<<800, 512>>>(l1w, l1fw, idx);
    k_main<<<MAX_TILES, NTHREADS, NSTAGE * STAGE_BYTES + 1024>>>(
        x, l1b, l1fb, l2w, l2b, outw, outb, out);
}

// round 8
// speedup vs baseline: 1.1022x; 1.1022x over previous
#include <cuda_runtime.h>
#include <cstdint>

#define NCOUNT 8
#define B_TOTAL 16384
#define L1 3072
#define M_TILE 64
#define KCHUNK 64
#define NCHUNK 48
#define MAX_TILES (B_TOTAL / M_TILE + NCOUNT)   // 264
#define NTHREADS 256
#define NSTAGE 3
#define ROW_STRIDE 272u                          // 256B data + 16B stagger (bank spread)
#define X_BYTES (64u * ROW_STRIDE)               // 17408
#define STAGE_BYTES (X_BYTES + 16u * ROW_STRIDE) // 21760
#define TX_BYTES (80u * 256u)                    // 20480 expected bytes per stage fill

// ---------------- device scratch ----------------
__device__ int   g_fill[NCOUNT];            // zeroed at load; re-zeroed by k_main blk0
__device__ int   g_rows2[NCOUNT][B_TOTAL];
__device__ float g_wcomb[NCOUNT * 16 * L1]; // combined l1_w[bucket] + l1f_w

#define FMA2(d, a, b) asm("fma.rn.f32x2 %0, %1, %2, %0;" : "+l"(d) : "l"(a), "l"(b))

__device__ __forceinline__ uint32_t smem_u32(const void* p) {
    return (uint32_t)__cvta_generic_to_shared((void*)p);
}

__device__ __forceinline__ void mbar_wait(uint32_t addr, uint32_t parity) {
    uint32_t done;
    asm volatile(
        "{\n\t.reg .pred p;\n\t"
        "mbarrier.try_wait.parity.acquire.cta.shared::cta.b64 p, [%1], %2;\n\t"
        "selp.b32 %0, 1, 0, p;\n\t}"
        : "=r"(done) : "r"(addr), "r"(parity) : "memory");
    if (!done) {
        asm volatile(
            "{\n\t.reg .pred P1;\n\t"
            "WL%=:\n\t"
            "mbarrier.try_wait.parity.acquire.cta.shared::cta.b64 P1, [%0], %1, 0x989680;\n\t"
            "@P1 bra.uni WD%=;\n\t"
            "bra.uni WL%=;\n\t"
            "WD%=:\n\t}"
            :: "r"(addr), "r"(parity) : "memory");
    }
}

// ---------------- prep: combined weights + bucket scatter ----------------
__global__ void k_prep(const float* __restrict__ l1w, const float* __restrict__ l1fw,
                       const int* __restrict__ idx)
{
    if (blockIdx.x < 768) {
        int e = blockIdx.x * 512 + threadIdx.x;     // 768*512 == 8*16*3072 exactly
        int k = e % L1;
        int r = (e / L1) % 16;
        g_wcomb[e] = l1w[e] + l1fw[r * L1 + k];
    } else {
        __shared__ int s_cnt[NCOUNT];
        __shared__ int s_base[NCOUNT];
        int tid = threadIdx.x;
        int i = (blockIdx.x - 768) * 512 + tid;
        int lane = tid & 31;
        if (tid < NCOUNT) s_cnt[tid] = 0;
        __syncthreads();
        int c = idx[i];
        unsigned mask = __match_any_sync(0xffffffffu, c);
        int leader = __ffs(mask) - 1;
        int rank = __popc(mask & ((1u << lane) - 1u));
        int wb = 0;
        if (lane == leader) wb = atomicAdd(&s_cnt[c], __popc(mask));
        wb = __shfl_sync(mask, wb, leader);
        __syncthreads();
        if (tid < NCOUNT) s_base[tid] = s_cnt[tid] ? atomicAdd(&g_fill[tid], s_cnt[tid]) : 0;
        __syncthreads();
        g_rows2[c][s_base[c] + wb + rank] = i;
    }
}

// ---------------- main kernel ----------------
// dyn smem: 3 stages x [x: 64 rows * 272B | w: 16 rows * 272B] = 65280 B
extern __shared__ char s_dyn_raw[];

__global__ void __launch_bounds__(NTHREADS, 2)
k_main(const float* __restrict__ x,
       const float* __restrict__ l1b, const float* __restrict__ l1fb,
       const float* __restrict__ l2w, const float* __restrict__ l2b,
       const float* __restrict__ outw, const float* __restrict__ outb,
       float* __restrict__ out)
{
    const int tid = threadIdx.x;

    // ---- tile -> (bucket, start, rows) from bucket counts ----
    int bucket = -1, startrow = 0, rows = 0;
    {
        int t = blockIdx.x;
#pragma unroll
        for (int c = 0; c < NCOUNT; c++) {
            int n = __ldg(&g_fill[c]);
            int nt = (n + M_TILE - 1) / M_TILE;
            if (bucket < 0) {
                if (t < nt) {
                    bucket = c; startrow = t * M_TILE;
                    rows = n - startrow; if (rows > M_TILE) rows = M_TILE;
                } else t -= nt;
            }
        }
    }
    if (bucket < 0) return;

    __shared__ int   s_rows[M_TILE];
    __shared__ float s_wpad[1024];
    __shared__ float s_outw[32], s_l2b[32], s_bc[16];
    __shared__ float s_outb;
    __shared__ __align__(8) unsigned long long s_mbar[NSTAGE];

    if (tid < M_TILE) {
        int mi = tid < rows ? tid : rows - 1;
        s_rows[tid] = g_rows2[bucket][startrow + mi];
    }
#pragma unroll
    for (int i = 0; i < 4; i++) {
        int e = tid + NTHREADS * i;
        int o = e >> 5, j = e & 31;
        s_wpad[e] = (j < 30) ? l2w[(bucket * 32 + o) * 30 + j] : 0.f;
    }
    if (tid < 32) { s_outw[tid] = outw[bucket * 32 + tid]; s_l2b[tid] = l2b[bucket * 32 + tid]; }
    if (tid < 16) s_bc[tid] = l1b[bucket * 16 + tid] + l1fb[tid];
    if (tid == 0) {
        s_outb = outb[bucket];
#pragma unroll
        for (int s = 0; s < NSTAGE; s++)
            asm volatile("mbarrier.init.shared.b64 [%0], %1;"
                         :: "r"(smem_u32(&s_mbar[s])), "r"(1u) : "memory");
    }
    __syncthreads();

    char*    db   = s_dyn_raw;
    uint32_t db_u = smem_u32(db);
    uint32_t mb_addr[NSTAGE];
#pragma unroll
    for (int s = 0; s < NSTAGE; s++) mb_addr[s] = smem_u32(&s_mbar[s]);

    // loader: tid<64 -> x row tid; tid in [64,80) -> w row tid-64
    const float* ldsrc = 0;
    uint32_t     lddst_off = 0;
    if (tid < 64) {
        ldsrc = x + (size_t)s_rows[tid] * L1;
        lddst_off = (uint32_t)tid * ROW_STRIDE;
    } else if (tid < 80) {
        ldsrc = g_wcomb + (size_t)(bucket * 16 + (tid - 64)) * L1;
        lddst_off = X_BYTES + (uint32_t)(tid - 64) * ROW_STRIDE;
    }

#define ISSUE(cc)                                                                      \
    do {                                                                               \
        int stg_ = (cc) % NSTAGE;                                                      \
        if (tid == 0)                                                                  \
            asm volatile("mbarrier.arrive.expect_tx.shared.b64 _, [%0], %1;"           \
                         :: "r"(mb_addr[stg_]), "r"((uint32_t)TX_BYTES) : "memory");   \
        if (tid < 80) {                                                                \
            uint32_t dst_ = db_u + (uint32_t)stg_ * STAGE_BYTES + lddst_off;           \
            const float* src_ = ldsrc + (cc) * KCHUNK;                                 \
            asm volatile(                                                              \
                "cp.async.bulk.shared::cluster.global.mbarrier::complete_tx::bytes "   \
                "[%0], [%1], %2, [%3];"                                                \
                :: "r"(dst_), "l"(src_), "r"(256u), "r"(mb_addr[stg_]) : "memory");    \
        }                                                                              \
    } while (0)

    ISSUE(0); ISSUE(1); ISSUE(2);

    // compute assignment: 8 warps = 8 k-split groups
    const int ks = tid >> 5;           // k-split 0..7 (2 float4 each)
    const int ng = (tid >> 4) & 1;     // 2 j-groups of 8
    const int mg = tid & 15;           // rows mg + 16r, r<4
    const int j0 = ng * 8;

    unsigned long long acc[4][8];
#pragma unroll
    for (int r = 0; r < 4; r++)
#pragma unroll
        for (int s = 0; s < 8; s++) acc[r][s] = 0ull;

#pragma unroll 1
    for (int c = 0; c < NCHUNK; c++) {
        const int stg = c % NSTAGE;
        mbar_wait(mb_addr[stg], (uint32_t)((c / NSTAGE) & 1));

        const char* xb = db + (uint32_t)stg * STAGE_BYTES;
        const char* wb = xb + X_BYTES;

#pragma unroll
        for (int i = 0; i < 2; i++) {
            int k4 = ks * 2 + i;                 // 0..15
            ulonglong2 wv[8];
#pragma unroll
            for (int s = 0; s < 8; s++)
                wv[s] = *(const ulonglong2*)(wb + (uint32_t)(j0 + s) * ROW_STRIDE + k4 * 16);
#pragma unroll
            for (int r = 0; r < 4; r++) {
                ulonglong2 xv = *(const ulonglong2*)(xb + (uint32_t)(mg + 16 * r) * ROW_STRIDE + k4 * 16);
#pragma unroll
                for (int s = 0; s < 8; s++) {
                    FMA2(acc[r][s], xv.x, wv[s].x);
                    FMA2(acc[r][s], xv.y, wv[s].y);
                }
            }
        }

        __syncthreads();                 // all readers done with stage before refill
        if (c + NSTAGE < NCHUNK) ISSUE(c + NSTAGE);
    }

    // ---- reduce k-split partials via smem (overlay on stage buffers; all bulk done) ----
    float* accs = (float*)s_dyn_raw;   // 8 * 64 * 17 floats = 34816 B
#pragma unroll
    for (int r = 0; r < 4; r++)
#pragma unroll
        for (int s = 0; s < 8; s++) {
            union { unsigned long long u; float2 f; } cv;
            cv.u = acc[r][s];
            accs[ks * 1088 + (mg + 16 * r) * 17 + (j0 + s)] = cv.f.x + cv.f.y;
        }
    __syncthreads();

    // ---- fused stage 2/3: one row per thread ----
    if (tid < M_TILE) {
        float t[16];
#pragma unroll
        for (int j = 0; j < 16; j++) {
            float a = 0.f;
#pragma unroll
            for (int p = 0; p < 8; p++) a += accs[p * 1088 + tid * 17 + j];
            t[j] = a + s_bc[j];
        }

        float v[32];
#pragma unroll
        for (int j = 0; j < 15; j++) {
            float a = t[j];
            v[j]      = fminf(a * a * (127.0f / 128.0f), 1.0f);
            v[15 + j] = fminf(fmaxf(a, 0.0f), 1.0f);
        }
        v[30] = 0.f; v[31] = 0.f;

        float res = t[15] + s_outb;
        const float4* wp4 = (const float4*)s_wpad;
#pragma unroll
        for (int o = 0; o < 32; o++) {
            float s = s_l2b[o];
#pragma unroll
            for (int q = 0; q < 8; q++) {
                float4 w = wp4[o * 8 + q];
                s += w.x * v[q * 4] + w.y * v[q * 4 + 1] + w.z * v[q * 4 + 2] + w.w * v[q * 4 + 3];
            }
            s = fminf(fmaxf(s, 0.0f), 1.0f);
            res += s * s_outw[o];
        }
        if (tid < rows) out[s_rows[tid]] = res;
    }

    __syncthreads();
    if (tid == 0) {
#pragma unroll
        for (int s = 0; s < NSTAGE; s++)
            asm volatile("mbarrier.inval.shared.b64 [%0];" :: "r"(mb_addr[s]) : "memory");
    }
    // reset bucket counters for the next graph replay (single co-resident wave)
    if (blockIdx.x == 0 && tid < NCOUNT) g_fill[tid] = 0;
}

// ---------------- launcher ----------------
extern "C" void kernel_launch(void* const* d_in, const int* in_sizes, int n_in,
                              void* d_out, int out_size)
{
    const float* x    = (const float*)d_in[0];
    const int*   idx  = (const int*)  d_in[1];
    const float* l1w  = (const float*)d_in[2];
    const float* l1b  = (const float*)d_in[3];
    const float* l1fw = (const float*)d_in[4];
    const float* l1fb = (const float*)d_in[5];
    const float* l2w  = (const float*)d_in[6];
    const float* l2b  = (const float*)d_in[7];
    const float* outw = (const float*)d_in[8];
    const float* outb = (const float*)d_in[9];
    float* out = (float*)d_out;

    static bool attr_set = false;
    if (!attr_set) {
        cudaFuncSetAttribute(k_main, cudaFuncAttributeMaxDynamicSharedMemorySize,
                             NSTAGE * STAGE_BYTES + 1024);
        attr_set = true;
    }

    k_prep<<<800, 512>>>(l1w, l1fw, idx);
    k_main<<<MAX_TILES, NTHREADS, NSTAGE * STAGE_BYTES + 1024>>>(
        x, l1b, l1fb, l2w, l2b, outw, outb, out);
}

// round 10
// speedup vs baseline: 1.3900x; 1.2611x over previous
#include <cuda_runtime.h>
#include <cstdint>

#define NCOUNT 8
#define B_TOTAL 16384
#define L1 3072
#define M_TILE 64
#define KCHUNK 128                               // floats per load-chunk (512B per row)
#define NCHUNK (L1 / KCHUNK)                     // 24
#define MAX_TILES (B_TOTAL / M_TILE + NCOUNT)    // 264
#define NTHREADS 256
#define NSTAGE 2
#define ROW_STRIDE 528u                          // 512B data + 16B stagger (bank spread)
#define X_BYTES (64u * ROW_STRIDE)               // 33792
#define STAGE_BYTES (X_BYTES + 16u * ROW_STRIDE) // 42240
#define TX_BYTES (80u * 512u)                    // 40960 expected bytes per stage fill

// ---------------- device scratch ----------------
__device__ int   g_fill[NCOUNT];            // zeroed at load; re-zeroed by k_main blk0
__device__ int   g_rows2[NCOUNT][B_TOTAL];
__device__ float g_wcomb[NCOUNT * 16 * L1]; // combined l1_w[bucket] + l1f_w

#define FMA2(d, a, b) asm("fma.rn.f32x2 %0, %1, %2, %0;" : "+l"(d) : "l"(a), "l"(b))

__device__ __forceinline__ uint32_t smem_u32(const void* p) {
    return (uint32_t)__cvta_generic_to_shared((void*)p);
}

__device__ __forceinline__ void mbar_wait(uint32_t addr, uint32_t parity) {
    uint32_t done;
    asm volatile(
        "{\n\t.reg .pred p;\n\t"
        "mbarrier.try_wait.parity.acquire.cta.shared::cta.b64 p, [%1], %2;\n\t"
        "selp.b32 %0, 1, 0, p;\n\t}"
        : "=r"(done) : "r"(addr), "r"(parity) : "memory");
    if (!done) {
        asm volatile(
            "{\n\t.reg .pred P1;\n\t"
            "WL%=:\n\t"
            "mbarrier.try_wait.parity.acquire.cta.shared::cta.b64 P1, [%0], %1, 0x989680;\n\t"
            "@P1 bra.uni WD%=;\n\t"
            "bra.uni WL%=;\n\t"
            "WD%=:\n\t}"
            :: "r"(addr), "r"(parity) : "memory");
    }
}

// ---------------- prep: combined weights + bucket scatter ----------------
__global__ void k_prep(const float* __restrict__ l1w, const float* __restrict__ l1fw,
                       const int* __restrict__ idx)
{
    if (blockIdx.x < 768) {
        int e = blockIdx.x * 512 + threadIdx.x;     // 768*512 == 8*16*3072 exactly
        int k = e % L1;
        int r = (e / L1) % 16;
        g_wcomb[e] = l1w[e] + l1fw[r * L1 + k];
    } else {
        __shared__ int s_cnt[NCOUNT];
        __shared__ int s_base[NCOUNT];
        int tid = threadIdx.x;
        int i = (blockIdx.x - 768) * 512 + tid;
        int lane = tid & 31;
        if (tid < NCOUNT) s_cnt[tid] = 0;
        __syncthreads();
        int c = idx[i];
        unsigned mask = __match_any_sync(0xffffffffu, c);
        int leader = __ffs(mask) - 1;
        int rank = __popc(mask & ((1u << lane) - 1u));
        int wb = 0;
        if (lane == leader) wb = atomicAdd(&s_cnt[c], __popc(mask));
        wb = __shfl_sync(mask, wb, leader);
        __syncthreads();
        if (tid < NCOUNT) s_base[tid] = s_cnt[tid] ? atomicAdd(&g_fill[tid], s_cnt[tid]) : 0;
        __syncthreads();
        g_rows2[c][s_base[c] + wb + rank] = i;
    }
}

// ---------------- main kernel ----------------
// dyn smem: 2 stages x [x: 64 rows * 528B | w: 16 rows * 528B] = 84480 B
extern __shared__ char s_dyn_raw[];

__global__ void __launch_bounds__(NTHREADS, 2)
k_main(const float* __restrict__ x,
       const float* __restrict__ l1b, const float* __restrict__ l1fb,
       const float* __restrict__ l2w, const float* __restrict__ l2b,
       const float* __restrict__ outw, const float* __restrict__ outb,
       float* __restrict__ out)
{
    const int tid = threadIdx.x;

    // ---- tile -> (bucket, start, rows) from bucket counts ----
    int bucket = -1, startrow = 0, rows = 0;
    {
        int t = blockIdx.x;
#pragma unroll
        for (int c = 0; c < NCOUNT; c++) {
            int n = __ldg(&g_fill[c]);
            int nt = (n + M_TILE - 1) / M_TILE;
            if (bucket < 0) {
                if (t < nt) {
                    bucket = c; startrow = t * M_TILE;
                    rows = n - startrow; if (rows > M_TILE) rows = M_TILE;
                } else t -= nt;
            }
        }
    }
    if (bucket < 0) return;

    __shared__ int   s_rows[M_TILE];
    __shared__ float s_wpad[1024];
    __shared__ float s_outw[32], s_l2b[32], s_bc[16];
    __shared__ float s_outb;
    __shared__ __align__(8) unsigned long long s_mbar[NSTAGE];

    if (tid < M_TILE) {
        int mi = tid < rows ? tid : rows - 1;
        s_rows[tid] = g_rows2[bucket][startrow + mi];
    }
#pragma unroll
    for (int i = 0; i < 4; i++) {
        int e = tid + NTHREADS * i;
        int o = e >> 5, j = e & 31;
        s_wpad[e] = (j < 30) ? l2w[(bucket * 32 + o) * 30 + j] : 0.f;
    }
    if (tid < 32) { s_outw[tid] = outw[bucket * 32 + tid]; s_l2b[tid] = l2b[bucket * 32 + tid]; }
    if (tid < 16) s_bc[tid] = l1b[bucket * 16 + tid] + l1fb[tid];
    if (tid == 0) {
        s_outb = outb[bucket];
#pragma unroll
        for (int s = 0; s < NSTAGE; s++)
            asm volatile("mbarrier.init.shared.b64 [%0], %1;"
                         :: "r"(smem_u32(&s_mbar[s])), "r"(1u) : "memory");
    }
    __syncthreads();

    char*    db   = s_dyn_raw;
    uint32_t db_u = smem_u32(db);
    uint32_t mb_addr[NSTAGE];
#pragma unroll
    for (int s = 0; s < NSTAGE; s++) mb_addr[s] = smem_u32(&s_mbar[s]);

    // loader: tid<64 -> x row tid; tid in [64,80) -> w row tid-64
    const float* ldsrc = 0;
    uint32_t     lddst_off = 0;
    if (tid < 64) {
        ldsrc = x + (size_t)s_rows[tid] * L1;
        lddst_off = (uint32_t)tid * ROW_STRIDE;
    } else if (tid < 80) {
        ldsrc = g_wcomb + (size_t)(bucket * 16 + (tid - 64)) * L1;
        lddst_off = X_BYTES + (uint32_t)(tid - 64) * ROW_STRIDE;
    }

#define ISSUE(cc)                                                                      \
    do {                                                                               \
        int stg_ = (cc) % NSTAGE;                                                      \
        if (tid == 0)                                                                  \
            asm volatile("mbarrier.arrive.expect_tx.shared.b64 _, [%0], %1;"           \
                         :: "r"(mb_addr[stg_]), "r"((uint32_t)TX_BYTES) : "memory");   \
        if (tid < 80) {                                                                \
            uint32_t dst_ = db_u + (uint32_t)stg_ * STAGE_BYTES + lddst_off;           \
            const float* src_ = ldsrc + (cc) * KCHUNK;                                 \
            asm volatile(                                                              \
                "cp.async.bulk.shared::cluster.global.mbarrier::complete_tx::bytes "   \
                "[%0], [%1], %2, [%3];"                                                \
                :: "r"(dst_), "l"(src_), "r"(512u), "r"(mb_addr[stg_]) : "memory");    \
        }                                                                              \
    } while (0)

    ISSUE(0); ISSUE(1);

    // compute assignment: 8 warps = 8 k-split groups
    const int ks = tid >> 5;           // k-split 0..7 (4 float4 each)
    const int ng = (tid >> 4) & 1;     // 2 j-groups of 8
    const int mg = tid & 15;           // rows mg + 16r, r<4
    const int j0 = ng * 8;

    unsigned long long acc[4][8];
#pragma unroll
    for (int r = 0; r < 4; r++)
#pragma unroll
        for (int s = 0; s < 8; s++) acc[r][s] = 0ull;

#pragma unroll 1
    for (int c = 0; c < NCHUNK; c++) {
        const int stg = c % NSTAGE;
        mbar_wait(mb_addr[stg], (uint32_t)((c / NSTAGE) & 1));

        const char* xb = db + (uint32_t)stg * STAGE_BYTES;
        const char* wb = xb + X_BYTES;

#pragma unroll
        for (int i = 0; i < 4; i++) {
            int k4 = ks * 4 + i;                 // 0..31
            ulonglong2 wv[8];
#pragma unroll
            for (int s = 0; s < 8; s++)
                wv[s] = *(const ulonglong2*)(wb + (uint32_t)(j0 + s) * ROW_STRIDE + k4 * 16);
#pragma unroll
            for (int r = 0; r < 4; r++) {
                ulonglong2 xv = *(const ulonglong2*)(xb + (uint32_t)(mg + 16 * r) * ROW_STRIDE + k4 * 16);
#pragma unroll
                for (int s = 0; s < 8; s++) {
                    FMA2(acc[r][s], xv.x, wv[s].x);
                    FMA2(acc[r][s], xv.y, wv[s].y);
                }
            }
        }

        __syncthreads();                 // all readers done with stage before refill
        if (c + NSTAGE < NCHUNK) ISSUE(c + NSTAGE);
    }

    // ---- reduce k-split partials via smem (overlay on stage buffers; all bulk done) ----
    float* accs = (float*)s_dyn_raw;   // 8 * 64 * 17 floats = 34816 B
#pragma unroll
    for (int r = 0; r < 4; r++)
#pragma unroll
        for (int s = 0; s < 8; s++) {
            union { unsigned long long u; float2 f; } cv;
            cv.u = acc[r][s];
            accs[ks * 1088 + (mg + 16 * r) * 17 + (j0 + s)] = cv.f.x + cv.f.y;
        }
    __syncthreads();

    // ---- fused stage 2/3: one row per thread ----
    if (tid < M_TILE) {
        float t[16];
#pragma unroll
        for (int j = 0; j < 16; j++) {
            float a = 0.f;
#pragma unroll
            for (int p = 0; p < 8; p++) a += accs[p * 1088 + tid * 17 + j];
            t[j] = a + s_bc[j];
        }

        float v[32];
#pragma unroll
        for (int j = 0; j < 15; j++) {
            float a = t[j];
            v[j]      = fminf(a * a * (127.0f / 128.0f), 1.0f);
            v[15 + j] = fminf(fmaxf(a, 0.0f), 1.0f);
        }
        v[30] = 0.f; v[31] = 0.f;

        float res = t[15] + s_outb;
        const float4* wp4 = (const float4*)s_wpad;
#pragma unroll
        for (int o = 0; o < 32; o++) {
            float s = s_l2b[o];
#pragma unroll
            for (int q = 0; q < 8; q++) {
                float4 w = wp4[o * 8 + q];
                s += w.x * v[q * 4] + w.y * v[q * 4 + 1] + w.z * v[q * 4 + 2] + w.w * v[q * 4 + 3];
            }
            s = fminf(fmaxf(s, 0.0f), 1.0f);
            res += s * s_outw[o];
        }
        if (tid < rows) out[s_rows[tid]] = res;
    }

    __syncthreads();
    if (tid == 0) {
#pragma unroll
        for (int s = 0; s < NSTAGE; s++)
            asm volatile("mbarrier.inval.shared.b64 [%0];" :: "r"(mb_addr[s]) : "memory");
    }
    // reset bucket counters for the next graph replay (single co-resident wave)
    if (blockIdx.x == 0 && tid < NCOUNT) g_fill[tid] = 0;
}

// ---------------- launcher ----------------
extern "C" void kernel_launch(void* const* d_in, const int* in_sizes, int n_in,
                              void* d_out, int out_size)
{
    const float* x    = (const float*)d_in[0];
    const int*   idx  = (const int*)  d_in[1];
    const float* l1w  = (const float*)d_in[2];
    const float* l1b  = (const float*)d_in[3];
    const float* l1fw = (const float*)d_in[4];
    const float* l1fb = (const float*)d_in[5];
    const float* l2w  = (const float*)d_in[6];
    const float* l2b  = (const float*)d_in[7];
    const float* outw = (const float*)d_in[8];
    const float* outb = (const float*)d_in[9];
    float* out = (float*)d_out;

    static bool attr_set = false;
    if (!attr_set) {
        cudaFuncSetAttribute(k_main, cudaFuncAttributeMaxDynamicSharedMemorySize,
                             NSTAGE * STAGE_BYTES + 1024);
        attr_set = true;
    }

    k_prep<<<800, 512>>>(l1w, l1fw, idx);
    k_main<<<MAX_TILES, NTHREADS, NSTAGE * STAGE_BYTES + 1024>>>(
        x, l1b, l1fb, l2w, l2b, outw, outb, out);
}

// round 11
// speedup vs baseline: 1.4345x; 1.0320x over previous
#include <cuda_runtime.h>
#include <cstdint>

#define NCOUNT 8
#define B_TOTAL 16384
#define L1 3072
#define M_TILE 64
#define KCHUNK 256                               // floats per load-chunk (1KB per row)
#define NCHUNK (L1 / KCHUNK)                     // 12
#define MAX_TILES (B_TOTAL / M_TILE + NCOUNT)    // 264
#define NTHREADS 256
#define NSTAGE 2
#define ROW_STRIDE 1040u                         // 1024B data + 16B stagger (bank spread)
#define X_BYTES (64u * ROW_STRIDE)               // 66560
#define STAGE_BYTES (X_BYTES + 16u * ROW_STRIDE) // 83200
#define TX_BYTES (80u * 1024u)                   // 81920 expected bytes per stage fill

// ---------------- device scratch ----------------
__device__ int   g_fill[NCOUNT];            // zeroed at load; re-zeroed by k_main blk0
__device__ int   g_rows2[NCOUNT][B_TOTAL];
__device__ float g_wcomb[NCOUNT * 16 * L1]; // combined l1_w[bucket] + l1f_w

#define FMA2(d, a, b) asm("fma.rn.f32x2 %0, %1, %2, %0;" : "+l"(d) : "l"(a), "l"(b))

__device__ __forceinline__ uint32_t smem_u32(const void* p) {
    return (uint32_t)__cvta_generic_to_shared((void*)p);
}

__device__ __forceinline__ void mbar_wait(uint32_t addr, uint32_t parity) {
    uint32_t done;
    asm volatile(
        "{\n\t.reg .pred p;\n\t"
        "mbarrier.try_wait.parity.acquire.cta.shared::cta.b64 p, [%1], %2;\n\t"
        "selp.b32 %0, 1, 0, p;\n\t}"
        : "=r"(done) : "r"(addr), "r"(parity) : "memory");
    if (!done) {
        asm volatile(
            "{\n\t.reg .pred P1;\n\t"
            "WL%=:\n\t"
            "mbarrier.try_wait.parity.acquire.cta.shared::cta.b64 P1, [%0], %1, 0x989680;\n\t"
            "@P1 bra.uni WD%=;\n\t"
            "bra.uni WL%=;\n\t"
            "WD%=:\n\t}"
            :: "r"(addr), "r"(parity) : "memory");
    }
}

// ---------------- prep: combined weights + bucket scatter ----------------
__global__ void k_prep(const float* __restrict__ l1w, const float* __restrict__ l1fw,
                       const int* __restrict__ idx)
{
    if (blockIdx.x < 768) {
        int e = blockIdx.x * 512 + threadIdx.x;     // 768*512 == 8*16*3072 exactly
        int k = e % L1;
        int r = (e / L1) % 16;
        g_wcomb[e] = l1w[e] + l1fw[r * L1 + k];
    } else {
        __shared__ int s_cnt[NCOUNT];
        __shared__ int s_base[NCOUNT];
        int tid = threadIdx.x;
        int i = (blockIdx.x - 768) * 512 + tid;
        int lane = tid & 31;
        if (tid < NCOUNT) s_cnt[tid] = 0;
        __syncthreads();
        int c = idx[i];
        unsigned mask = __match_any_sync(0xffffffffu, c);
        int leader = __ffs(mask) - 1;
        int rank = __popc(mask & ((1u << lane) - 1u));
        int wb = 0;
        if (lane == leader) wb = atomicAdd(&s_cnt[c], __popc(mask));
        wb = __shfl_sync(mask, wb, leader);
        __syncthreads();
        if (tid < NCOUNT) s_base[tid] = s_cnt[tid] ? atomicAdd(&g_fill[tid], s_cnt[tid]) : 0;
        __syncthreads();
        g_rows2[c][s_base[c] + wb + rank] = i;
    }
}

// ---------------- main kernel ----------------
// dyn smem: 2 stages x [x: 64 rows * 1040B | w: 16 rows * 1040B] = 166400 B
extern __shared__ char s_dyn_raw[];

__global__ void __launch_bounds__(NTHREADS, 1)
k_main(const float* __restrict__ x,
       const float* __restrict__ l1b, const float* __restrict__ l1fb,
       const float* __restrict__ l2w, const float* __restrict__ l2b,
       const float* __restrict__ outw, const float* __restrict__ outb,
       float* __restrict__ out)
{
    const int tid = threadIdx.x;

    // ---- tile -> (bucket, start, rows) from bucket counts ----
    int bucket = -1, startrow = 0, rows = 0;
    {
        int t = blockIdx.x;
#pragma unroll
        for (int c = 0; c < NCOUNT; c++) {
            int n = __ldg(&g_fill[c]);
            int nt = (n + M_TILE - 1) / M_TILE;
            if (bucket < 0) {
                if (t < nt) {
                    bucket = c; startrow = t * M_TILE;
                    rows = n - startrow; if (rows > M_TILE) rows = M_TILE;
                } else t -= nt;
            }
        }
    }
    if (bucket < 0) return;

    __shared__ int   s_rows[M_TILE];
    __shared__ float s_wpad[1024];
    __shared__ float s_outw[32], s_l2b[32], s_bc[16];
    __shared__ float s_outb;
    __shared__ __align__(8) unsigned long long s_mbar[NSTAGE];

    if (tid < M_TILE) {
        int mi = tid < rows ? tid : rows - 1;
        s_rows[tid] = g_rows2[bucket][startrow + mi];
    }
#pragma unroll
    for (int i = 0; i < 4; i++) {
        int e = tid + NTHREADS * i;
        int o = e >> 5, j = e & 31;
        s_wpad[e] = (j < 30) ? l2w[(bucket * 32 + o) * 30 + j] : 0.f;
    }
    if (tid < 32) { s_outw[tid] = outw[bucket * 32 + tid]; s_l2b[tid] = l2b[bucket * 32 + tid]; }
    if (tid < 16) s_bc[tid] = l1b[bucket * 16 + tid] + l1fb[tid];
    if (tid == 0) {
        s_outb = outb[bucket];
#pragma unroll
        for (int s = 0; s < NSTAGE; s++)
            asm volatile("mbarrier.init.shared.b64 [%0], %1;"
                         :: "r"(smem_u32(&s_mbar[s])), "r"(1u) : "memory");
    }
    __syncthreads();

    char*    db   = s_dyn_raw;
    uint32_t db_u = smem_u32(db);
    uint32_t mb_addr[NSTAGE];
#pragma unroll
    for (int s = 0; s < NSTAGE; s++) mb_addr[s] = smem_u32(&s_mbar[s]);

    // loader: tid<64 -> x row tid; tid in [64,80) -> w row tid-64
    const float* ldsrc = 0;
    uint32_t     lddst_off = 0;
    if (tid < 64) {
        ldsrc = x + (size_t)s_rows[tid] * L1;
        lddst_off = (uint32_t)tid * ROW_STRIDE;
    } else if (tid < 80) {
        ldsrc = g_wcomb + (size_t)(bucket * 16 + (tid - 64)) * L1;
        lddst_off = X_BYTES + (uint32_t)(tid - 64) * ROW_STRIDE;
    }

#define ISSUE(cc)                                                                      \
    do {                                                                               \
        int stg_ = (cc) % NSTAGE;                                                      \
        if (tid == 0)                                                                  \
            asm volatile("mbarrier.arrive.expect_tx.shared.b64 _, [%0], %1;"           \
                         :: "r"(mb_addr[stg_]), "r"((uint32_t)TX_BYTES) : "memory");   \
        if (tid < 80) {                                                                \
            uint32_t dst_ = db_u + (uint32_t)stg_ * STAGE_BYTES + lddst_off;           \
            const float* src_ = ldsrc + (cc) * KCHUNK;                                 \
            asm volatile(                                                              \
                "cp.async.bulk.shared::cluster.global.mbarrier::complete_tx::bytes "   \
                "[%0], [%1], %2, [%3];"                                                \
                :: "r"(dst_), "l"(src_), "r"(1024u), "r"(mb_addr[stg_]) : "memory");   \
        }                                                                              \
    } while (0)

    ISSUE(0); ISSUE(1);

    // compute assignment: 8 warps = 8 k-split groups
    const int ks = tid >> 5;           // k-split 0..7 (8 float4 each)
    const int ng = (tid >> 4) & 1;     // 2 j-groups of 8
    const int mg = tid & 15;           // rows mg + 16r, r<4
    const int j0 = ng * 8;

    unsigned long long acc[4][8];
#pragma unroll
    for (int r = 0; r < 4; r++)
#pragma unroll
        for (int s = 0; s < 8; s++) acc[r][s] = 0ull;

#pragma unroll 1
    for (int c = 0; c < NCHUNK; c++) {
        const int stg = c % NSTAGE;
        mbar_wait(mb_addr[stg], (uint32_t)((c / NSTAGE) & 1));

        const char* xb = db + (uint32_t)stg * STAGE_BYTES;
        const char* wb = xb + X_BYTES;

#pragma unroll
        for (int i = 0; i < 8; i++) {
            int k4 = ks * 8 + i;                 // 0..63
            ulonglong2 wv[8];
#pragma unroll
            for (int s = 0; s < 8; s++)
                wv[s] = *(const ulonglong2*)(wb + (uint32_t)(j0 + s) * ROW_STRIDE + k4 * 16);
#pragma unroll
            for (int r = 0; r < 4; r++) {
                ulonglong2 xv = *(const ulonglong2*)(xb + (uint32_t)(mg + 16 * r) * ROW_STRIDE + k4 * 16);
#pragma unroll
                for (int s = 0; s < 8; s++) {
                    FMA2(acc[r][s], xv.x, wv[s].x);
                    FMA2(acc[r][s], xv.y, wv[s].y);
                }
            }
        }

        __syncthreads();                 // all readers done with stage before refill
        if (c + NSTAGE < NCHUNK) ISSUE(c + NSTAGE);
    }

    // ---- reduce k-split partials via smem (overlay on stage buffers; all bulk done) ----
    float* accs = (float*)s_dyn_raw;   // 8 * 64 * 17 floats = 34816 B
#pragma unroll
    for (int r = 0; r < 4; r++)
#pragma unroll
        for (int s = 0; s < 8; s++) {
            union { unsigned long long u; float2 f; } cv;
            cv.u = acc[r][s];
            accs[ks * 1088 + (mg + 16 * r) * 17 + (j0 + s)] = cv.f.x + cv.f.y;
        }
    __syncthreads();

    // ---- fused stage 2/3: one row per thread ----
    if (tid < M_TILE) {
        float t[16];
#pragma unroll
        for (int j = 0; j < 16; j++) {
            float a = 0.f;
#pragma unroll
            for (int p = 0; p < 8; p++) a += accs[p * 1088 + tid * 17 + j];
            t[j] = a + s_bc[j];
        }

        float v[32];
#pragma unroll
        for (int j = 0; j < 15; j++) {
            float a = t[j];
            v[j]      = fminf(a * a * (127.0f / 128.0f), 1.0f);
            v[15 + j] = fminf(fmaxf(a, 0.0f), 1.0f);
        }
        v[30] = 0.f; v[31] = 0.f;

        float res = t[15] + s_outb;
        const float4* wp4 = (const float4*)s_wpad;
#pragma unroll
        for (int o = 0; o < 32; o++) {
            float s = s_l2b[o];
#pragma unroll
            for (int q = 0; q < 8; q++) {
                float4 w = wp4[o * 8 + q];
                s += w.x * v[q * 4] + w.y * v[q * 4 + 1] + w.z * v[q * 4 + 2] + w.w * v[q * 4 + 3];
            }
            s = fminf(fmaxf(s, 0.0f), 1.0f);
            res += s * s_outw[o];
        }
        if (tid < rows) out[s_rows[tid]] = res;
    }

    __syncthreads();
    if (tid == 0) {
#pragma unroll
        for (int s = 0; s < NSTAGE; s++)
            asm volatile("mbarrier.inval.shared.b64 [%0];" :: "r"(mb_addr[s]) : "memory");
    }
    // reset bucket counters for the next graph replay (single co-resident wave)
    if (blockIdx.x == 0 && tid < NCOUNT) g_fill[tid] = 0;
}

// ---------------- launcher ----------------
extern "C" void kernel_launch(void* const* d_in, const int* in_sizes, int n_in,
                              void* d_out, int out_size)
{
    const float* x    = (const float*)d_in[0];
    const int*   idx  = (const int*)  d_in[1];
    const float* l1w  = (const float*)d_in[2];
    const float* l1b  = (const float*)d_in[3];
    const float* l1fw = (const float*)d_in[4];
    const float* l1fb = (const float*)d_in[5];
    const float* l2w  = (const float*)d_in[6];
    const float* l2b  = (const float*)d_in[7];
    const float* outw = (const float*)d_in[8];
    const float* outb = (const float*)d_in[9];
    float* out = (float*)d_out;

    static bool attr_set = false;
    if (!attr_set) {
        cudaFuncSetAttribute(k_main, cudaFuncAttributeMaxDynamicSharedMemorySize,
                             NSTAGE * STAGE_BYTES + 1024);
        attr_set = true;
    }

    k_prep<<<800, 512>>>(l1w, l1fw, idx);
    k_main<<<MAX_TILES, NTHREADS, NSTAGE * STAGE_BYTES + 1024>>>(
        x, l1b, l1fb, l2w, l2b, outw, outb, out);
}